// round 1
// baseline (speedup 1.0000x reference)
#include <cuda_runtime.h>
#include <math.h>

// Problem constants
#define KU 128      // users (K)
#define MD 1024     // M
#define NU 128      // N (== KU)
#define MCHUNKS 8   // m-split for stage-2 partials
static __device__ __constant__ float N0F = 1e-11f;  // 10^(-80/10)/1000

// Scratch (static __device__ — no allocation)
__device__ float d_h_re[KU * MD];
__device__ float d_h_im[KU * MD];
__device__ float d_gp_re[MCHUNKS * KU * NU];
__device__ float d_gp_im[MCHUNKS * KU * NU];
__device__ float d_R[KU];

// ---------------------------------------------------------------------------
// Kernel 1: h = h_d + A v  (complex), warp-per-row, HBM-bound (134 MB reads)
// grid 1024 x 256 threads = 8192 warps; 131072 rows -> 16 rows/warp
// ---------------------------------------------------------------------------
__global__ __launch_bounds__(256) void k1_channel(
    const float* __restrict__ Wv,
    const float* __restrict__ Ar,
    const float* __restrict__ Ai,
    const float* __restrict__ hdr,
    const float* __restrict__ hdi)
{
    const int lane = threadIdx.x & 31;
    const int warp = (blockIdx.x * blockDim.x + threadIdx.x) >> 5;

    // v_re / v_im: 128 floats each, one float4 per lane
    const float4 vr = reinterpret_cast<const float4*>(Wv)[lane];
    const float4 vi = reinterpret_cast<const float4*>(Wv + 128)[lane];

    const int row0 = warp * 16;
#pragma unroll 4
    for (int i = 0; i < 16; i++) {
        const int row = row0 + i;
        const float4 a = reinterpret_cast<const float4*>(Ar + (size_t)row * NU)[lane];
        const float4 b = reinterpret_cast<const float4*>(Ai + (size_t)row * NU)[lane];

        float sre = a.x * vr.x + a.y * vr.y + a.z * vr.z + a.w * vr.w
                  - (b.x * vi.x + b.y * vi.y + b.z * vi.z + b.w * vi.w);
        float sim = b.x * vr.x + b.y * vr.y + b.z * vr.z + b.w * vr.w
                  + (a.x * vi.x + a.y * vi.y + a.z * vi.z + a.w * vi.w);

#pragma unroll
        for (int off = 16; off; off >>= 1) {
            sre += __shfl_xor_sync(0xffffffffu, sre, off);
            sim += __shfl_xor_sync(0xffffffffu, sim, off);
        }
        if (lane == 0) {
            d_h_re[row] = hdr[row] + sre;
            d_h_im[row] = hdi[row] + sim;
        }
    }
}

// ---------------------------------------------------------------------------
// Kernel 2: g = h @ (W_re + i W_im), partials per m-chunk.
// grid (8 m-chunks, 16 k-tiles), 128 threads (thread = output column n).
// Each block: 8 k rows x 128 m x 128 n. W slice read once per block (L2).
// ---------------------------------------------------------------------------
__global__ __launch_bounds__(128) void k2_gemm(const float* __restrict__ Wv)
{
    __shared__ float hs_re[8][128];
    __shared__ float hs_im[8][128];

    const int n  = threadIdx.x;       // 0..127
    const int mc = blockIdx.x;        // 0..7
    const int kt = blockIdx.y;        // 0..15
    const int k0 = kt * 8;
    const int m0 = mc * 128;

    // cooperative load of h tile (coalesced)
    for (int i = threadIdx.x; i < 8 * 128; i += 128) {
        const int kk = i >> 7, mm = i & 127;
        hs_re[kk][mm] = d_h_re[(k0 + kk) * MD + m0 + mm];
        hs_im[kk][mm] = d_h_im[(k0 + kk) * MD + m0 + mm];
    }
    __syncthreads();

    float are[8], aim[8];
#pragma unroll
    for (int kk = 0; kk < 8; kk++) { are[kk] = 0.f; aim[kk] = 0.f; }

    // W row m (global index m0+m) lives at W_v[1 + m0 + m][*], row stride 256
    const float* Wbase = Wv + (size_t)(1 + m0) * 256;

    for (int m = 0; m < 128; m++) {
        const float wre = Wbase[m * 256 + n];
        const float wim = Wbase[m * 256 + 128 + n];
#pragma unroll
        for (int kk = 0; kk < 8; kk++) {
            const float hre = hs_re[kk][m];
            const float him = hs_im[kk][m];
            are[kk] = fmaf(hre, wre, fmaf(-him, wim, are[kk]));
            aim[kk] = fmaf(hre, wim, fmaf( him, wre, aim[kk]));
        }
    }

#pragma unroll
    for (int kk = 0; kk < 8; kk++) {
        d_gp_re[mc * (KU * NU) + (k0 + kk) * NU + n] = are[kk];
        d_gp_im[mc * (KU * NU) + (k0 + kk) * NU + n] = aim[kk];
    }
}

// ---------------------------------------------------------------------------
// Kernel 3: per-k: reduce partials, mag, row-sum, R[k]. grid 128 x 128 thr.
// ---------------------------------------------------------------------------
__global__ __launch_bounds__(128) void k3_rate()
{
    const int k = blockIdx.x;
    const int n = threadIdx.x;

    float gre = 0.f, gim = 0.f;
#pragma unroll
    for (int p = 0; p < MCHUNKS; p++) {
        gre += d_gp_re[p * (KU * NU) + k * NU + n];
        gim += d_gp_im[p * (KU * NU) + k * NU + n];
    }
    const float mag = sqrtf(gre * gre + gim * gim);

    __shared__ float red[128];
    __shared__ float sig_s;
    red[n] = mag;
    if (n == k) sig_s = mag;
    __syncthreads();
#pragma unroll
    for (int s = 64; s > 0; s >>= 1) {
        if (n < s) red[n] += red[n + s];
        __syncthreads();
    }
    if (n == 0) {
        const float sig = sig_s;
        d_R[k] = sig / (red[0] - sig + N0F);
    }
}

// ---------------------------------------------------------------------------
// Kernel 4: out = -sum(R) * 1e6
// ---------------------------------------------------------------------------
__global__ __launch_bounds__(128) void k4_final(float* __restrict__ out)
{
    const int n = threadIdx.x;
    __shared__ float red[128];
    red[n] = d_R[n];
    __syncthreads();
#pragma unroll
    for (int s = 64; s > 0; s >>= 1) {
        if (n < s) red[n] += red[n + s];
        __syncthreads();
    }
    if (n == 0) out[0] = -red[0] * 1e6f;
}

// ---------------------------------------------------------------------------
extern "C" void kernel_launch(void* const* d_in, const int* in_sizes, int n_in,
                              void* d_out, int out_size)
{
    const float* Wv  = (const float*)d_in[0];  // (1025, 256)
    const float* Ar  = (const float*)d_in[1];  // (128, 1024, 128)
    const float* Ai  = (const float*)d_in[2];
    const float* hdr = (const float*)d_in[3];  // (128, 1024)
    const float* hdi = (const float*)d_in[4];

    k1_channel<<<1024, 256>>>(Wv, Ar, Ai, hdr, hdi);
    k2_gemm<<<dim3(MCHUNKS, 16), 128>>>(Wv);
    k3_rate<<<KU, 128>>>();
    k4_final<<<1, 128>>>((float*)d_out);
}

// round 2
// speedup vs baseline: 1.6181x; 1.6181x over previous
#include <cuda_runtime.h>
#include <math.h>

#define KU 128      // users (K)
#define MD 1024     // M
#define NU 128      // N (== KU)
#define MCHUNKS 8   // m-split for stage-2 partials
static __device__ __constant__ float N0F = 1e-11f;  // 10^(-80/10)/1000

// Scratch (static __device__ — no allocation)
__device__ float d_h_re[KU * MD];
__device__ float d_h_im[KU * MD];
__device__ float d_gp_re[MCHUNKS * KU * NU];
__device__ float d_gp_im[MCHUNKS * KU * NU];
__device__ float d_R[KU];

__device__ __forceinline__ float dot4(float4 a, float4 b) {
    return fmaf(a.x, b.x, fmaf(a.y, b.y, fmaf(a.z, b.z, a.w * b.w)));
}

// ---------------------------------------------------------------------------
// Kernel 1: h = h_d + A v (complex). HBM-bound (134 MB reads).
// Warp = two 16-lane halves; each half owns one row per group (8 floats/lane).
// 4-stage shfl reduction instead of 5; unroll 4 -> 16 LDG.128 in flight/warp.
// ---------------------------------------------------------------------------
__global__ __launch_bounds__(256) void k1_channel(
    const float* __restrict__ Wv,
    const float* __restrict__ Ar,
    const float* __restrict__ Ai,
    const float* __restrict__ hdr,
    const float* __restrict__ hdi)
{
    const int lane = threadIdx.x & 31;
    const int warp = (blockIdx.x * blockDim.x + threadIdx.x) >> 5;
    const int c    = lane & 15;   // position within half
    const int sub  = lane >> 4;   // which row of the pair

    const float4* vr4 = reinterpret_cast<const float4*>(Wv);
    const float4* vi4 = reinterpret_cast<const float4*>(Wv + 128);
    const float4 v0r = vr4[c], v1r = vr4[c + 16];
    const float4 v0i = vi4[c], v1i = vi4[c + 16];

    const int row0 = warp * 16;
#pragma unroll 4
    for (int g = 0; g < 8; g++) {
        const int row = row0 + g * 2 + sub;
        const float4* ar = reinterpret_cast<const float4*>(Ar + (size_t)row * NU);
        const float4* ai = reinterpret_cast<const float4*>(Ai + (size_t)row * NU);
        const float4 a0 = ar[c], a1 = ar[c + 16];
        const float4 b0 = ai[c], b1 = ai[c + 16];

        float sre = dot4(a0, v0r) + dot4(a1, v1r) - dot4(b0, v0i) - dot4(b1, v1i);
        float sim = dot4(b0, v0r) + dot4(b1, v1r) + dot4(a0, v0i) + dot4(a1, v1i);

#pragma unroll
        for (int off = 8; off; off >>= 1) {
            sre += __shfl_xor_sync(0xffffffffu, sre, off);
            sim += __shfl_xor_sync(0xffffffffu, sim, off);
        }
        if (c == 0) {
            d_h_re[row] = hdr[row] + sre;
            d_h_im[row] = hdi[row] + sim;
        }
    }
}

// ---------------------------------------------------------------------------
// Kernel 2: g = h @ (W_re + i W_im), partials per m-chunk.
// grid (8 mc, 16 kt), 256 threads. thread = (n, kk-group of 4).
// W staged through smem in 32-row subtiles; h tile transposed [m][kk] so a
// single broadcast LDS.128 fetches 4 k-rows. Per-m: 2 LDS + 2 LDS.128 + 16 FMA.
// ---------------------------------------------------------------------------
__global__ __launch_bounds__(256) void k2_gemm(const float* __restrict__ Wv)
{
    __shared__ float hsrt[128 * 8];   // [m][kk] transposed
    __shared__ float hsit[128 * 8];
    __shared__ float ws[32 * 256];    // 32 W rows (re|im), 32 KB

    const int tid = threadIdx.x;
    const int n   = tid & 127;        // output column
    const int g   = tid >> 7;         // kk group (0/1): kk = g*4 .. g*4+3
    const int mc  = blockIdx.x;       // 0..7
    const int kt  = blockIdx.y;       // 0..15
    const int k0  = kt * 8;
    const int m0  = mc * 128;

    // h tile -> transposed smem (coalesced global reads)
    for (int i = tid; i < 8 * 128; i += 256) {
        const int kk = i >> 7, mm = i & 127;
        hsrt[mm * 8 + kk] = d_h_re[(k0 + kk) * MD + m0 + mm];
        hsit[mm * 8 + kk] = d_h_im[(k0 + kk) * MD + m0 + mm];
    }

    float are[4] = {0.f, 0.f, 0.f, 0.f};
    float aim[4] = {0.f, 0.f, 0.f, 0.f};

    const float4* wsrc = reinterpret_cast<const float4*>(Wv + (size_t)(1 + m0) * 256);
    float4* wdst = reinterpret_cast<float4*>(ws);

    for (int ms = 0; ms < 128; ms += 32) {
        __syncthreads();              // readers of previous subtile done
        // 32 rows x 256 floats = 2048 float4, 8 per thread, coalesced
#pragma unroll
        for (int s = 0; s < 8; s++)
            wdst[s * 256 + tid] = wsrc[(size_t)(ms >> 2) * 256 + s * 256 + tid];
        __syncthreads();

#pragma unroll 8
        for (int mi = 0; mi < 32; mi++) {
            const int m = ms + mi;
            const float wre = ws[mi * 256 + n];
            const float wim = ws[mi * 256 + 128 + n];
            const float4 hre = *reinterpret_cast<const float4*>(&hsrt[m * 8 + g * 4]);
            const float4 him = *reinterpret_cast<const float4*>(&hsit[m * 8 + g * 4]);

            are[0] = fmaf(hre.x, wre, fmaf(-him.x, wim, are[0]));
            aim[0] = fmaf(hre.x, wim, fmaf( him.x, wre, aim[0]));
            are[1] = fmaf(hre.y, wre, fmaf(-him.y, wim, are[1]));
            aim[1] = fmaf(hre.y, wim, fmaf( him.y, wre, aim[1]));
            are[2] = fmaf(hre.z, wre, fmaf(-him.z, wim, are[2]));
            aim[2] = fmaf(hre.z, wim, fmaf( him.z, wre, aim[2]));
            are[3] = fmaf(hre.w, wre, fmaf(-him.w, wim, are[3]));
            aim[3] = fmaf(hre.w, wim, fmaf( him.w, wre, aim[3]));
        }
    }

#pragma unroll
    for (int j = 0; j < 4; j++) {
        const int kk = k0 + g * 4 + j;
        d_gp_re[mc * (KU * NU) + kk * NU + n] = are[j];
        d_gp_im[mc * (KU * NU) + kk * NU + n] = aim[j];
    }
}

// ---------------------------------------------------------------------------
// Kernel 3: per-k: reduce partials, mag, row-sum, R[k]. grid 128 x 128 thr.
// ---------------------------------------------------------------------------
__global__ __launch_bounds__(128) void k3_rate()
{
    const int k = blockIdx.x;
    const int n = threadIdx.x;

    float gre = 0.f, gim = 0.f;
#pragma unroll
    for (int p = 0; p < MCHUNKS; p++) {
        gre += d_gp_re[p * (KU * NU) + k * NU + n];
        gim += d_gp_im[p * (KU * NU) + k * NU + n];
    }
    const float mag = sqrtf(gre * gre + gim * gim);

    __shared__ float red[128];
    __shared__ float sig_s;
    red[n] = mag;
    if (n == k) sig_s = mag;
    __syncthreads();
#pragma unroll
    for (int s = 64; s > 0; s >>= 1) {
        if (n < s) red[n] += red[n + s];
        __syncthreads();
    }
    if (n == 0) {
        const float sig = sig_s;
        d_R[k] = sig / (red[0] - sig + N0F);
    }
}

// ---------------------------------------------------------------------------
// Kernel 4: out = -sum(R) * 1e6
// ---------------------------------------------------------------------------
__global__ __launch_bounds__(128) void k4_final(float* __restrict__ out)
{
    const int n = threadIdx.x;
    __shared__ float red[128];
    red[n] = d_R[n];
    __syncthreads();
#pragma unroll
    for (int s = 64; s > 0; s >>= 1) {
        if (n < s) red[n] += red[n + s];
        __syncthreads();
    }
    if (n == 0) out[0] = -red[0] * 1e6f;
}

// ---------------------------------------------------------------------------
extern "C" void kernel_launch(void* const* d_in, const int* in_sizes, int n_in,
                              void* d_out, int out_size)
{
    const float* Wv  = (const float*)d_in[0];  // (1025, 256)
    const float* Ar  = (const float*)d_in[1];  // (128, 1024, 128)
    const float* Ai  = (const float*)d_in[2];
    const float* hdr = (const float*)d_in[3];  // (128, 1024)
    const float* hdi = (const float*)d_in[4];

    k1_channel<<<1024, 256>>>(Wv, Ar, Ai, hdr, hdi);
    k2_gemm<<<dim3(MCHUNKS, 16), 256>>>(Wv);
    k3_rate<<<KU, 128>>>();
    k4_final<<<1, 128>>>((float*)d_out);
}

// round 4
// speedup vs baseline: 1.7140x; 1.0592x over previous
#include <cuda_runtime.h>
#include <math.h>

#define KU 128      // users (K)
#define MD 1024     // M
#define NU 128      // N (== KU)
#define KT 8        // k rows per block tile
#define MCH 32      // m rows per block chunk
#define NKT (KU / KT)    // 16
#define NMC (MD / MCH)   // 32
static __device__ __constant__ float N0F = 1e-11f;  // 10^(-80/10)/1000

// Scratch (static __device__ — no allocation)
__device__ float d_gp_re[NMC * KU * NU];   // per-m-chunk partials of g
__device__ float d_gp_im[NMC * KU * NU];
__device__ float d_R[KU];
__device__ unsigned int d_ctr;             // zero-initialized; k3 resets it

__device__ __forceinline__ float dot4(float4 a, float4 b) {
    return fmaf(a.x, b.x, fmaf(a.y, b.y, fmaf(a.z, b.z, a.w * b.w)));
}

// ---------------------------------------------------------------------------
// Fused kernel: stage A computes h = h_d + A v for an (8k x 32m) tile
// (DRAM-bound, 256 KB of A per block), stage B immediately contracts the tile
// against W[m0:m0+32, :] (L2-resident) into g partials. FMA work of stage B
// hides under other blocks' stage-A DRAM streaming.
// grid (32 m-chunks, 16 k-tiles) x 256 threads.
// ---------------------------------------------------------------------------
__global__ __launch_bounds__(256) void k12_fused(
    const float* __restrict__ Wv,
    const float* __restrict__ Ar,
    const float* __restrict__ Ai,
    const float* __restrict__ hdr,
    const float* __restrict__ hdi)
{
    __shared__ float hsrt[MCH * 8];   // h_re transposed [m][kk]
    __shared__ float hsit[MCH * 8];   // h_im transposed [m][kk]

    const int tid  = threadIdx.x;
    const int lane = tid & 31;
    const int warp = tid >> 5;        // 0..7 == kk
    const int c    = lane & 15;       // position within 16-lane half
    const int sub  = lane >> 4;       // which row of the pair

    const int mc = blockIdx.x;        // 0..31
    const int kt = blockIdx.y;        // 0..15
    const int k0 = kt * KT;
    const int m0 = mc * MCH;

    // v_re / v_im (2 float4 per half-lane)
    const float4* vr4 = reinterpret_cast<const float4*>(Wv);
    const float4* vi4 = reinterpret_cast<const float4*>(Wv + 128);
    const float4 v0r = vr4[c], v1r = vr4[c + 16];
    const float4 v0i = vi4[c], v1i = vi4[c + 16];

    // ---- stage A: warp `warp` owns kk = warp, all 32 m's (contiguous 16 KB) ----
    const int kk = warp;
    const size_t rbase = (size_t)(k0 + kk) * MD + m0;
#pragma unroll 4
    for (int it = 0; it < 16; it++) {
        const int m   = it * 2 + sub;
        const size_t row = rbase + m;
        const float4* ar = reinterpret_cast<const float4*>(Ar + row * NU);
        const float4* ai = reinterpret_cast<const float4*>(Ai + row * NU);
        const float4 a0 = ar[c], a1 = ar[c + 16];
        const float4 b0 = ai[c], b1 = ai[c + 16];

        float sre = dot4(a0, v0r) + dot4(a1, v1r) - dot4(b0, v0i) - dot4(b1, v1i);
        float sim = dot4(b0, v0r) + dot4(b1, v1r) + dot4(a0, v0i) + dot4(a1, v1i);

#pragma unroll
        for (int off = 8; off; off >>= 1) {
            sre += __shfl_xor_sync(0xffffffffu, sre, off);
            sim += __shfl_xor_sync(0xffffffffu, sim, off);
        }
        if (c == 0) {
            hsrt[m * 8 + kk] = hdr[row] + sre;
            hsit[m * 8 + kk] = hdi[row] + sim;
        }
    }
    __syncthreads();

    // ---- stage B: g_partial[kk, n] += sum_m h[kk,m] * W[m0+m, n] (complex) ----
    const int n = tid & 127;          // output column
    const int g = tid >> 7;           // kk group: g*4 .. g*4+3
    float are[4] = {0.f, 0.f, 0.f, 0.f};
    float aim[4] = {0.f, 0.f, 0.f, 0.f};

    const float* Wb = Wv + (size_t)(1 + m0) * 256;   // W rows m0.., stride 256

#pragma unroll 4
    for (int m = 0; m < MCH; m++) {
        const float wre = __ldg(Wb + m * 256 + n);
        const float wim = __ldg(Wb + m * 256 + 128 + n);
        const float4 hre = *reinterpret_cast<const float4*>(&hsrt[m * 8 + g * 4]);
        const float4 him = *reinterpret_cast<const float4*>(&hsit[m * 8 + g * 4]);

        are[0] = fmaf(hre.x, wre, fmaf(-him.x, wim, are[0]));
        aim[0] = fmaf(hre.x, wim, fmaf( him.x, wre, aim[0]));
        are[1] = fmaf(hre.y, wre, fmaf(-him.y, wim, are[1]));
        aim[1] = fmaf(hre.y, wim, fmaf( him.y, wre, aim[1]));
        are[2] = fmaf(hre.z, wre, fmaf(-him.z, wim, are[2]));
        aim[2] = fmaf(hre.z, wim, fmaf( him.z, wre, aim[2]));
        are[3] = fmaf(hre.w, wre, fmaf(-him.w, wim, are[3]));
        aim[3] = fmaf(hre.w, wim, fmaf( him.w, wre, aim[3]));
    }

#pragma unroll
    for (int j = 0; j < 4; j++) {
        const int kidx = k0 + g * 4 + j;
        d_gp_re[mc * (KU * NU) + kidx * NU + n] = are[j];
        d_gp_im[mc * (KU * NU) + kidx * NU + n] = aim[j];
    }
}

// ---------------------------------------------------------------------------
// k3: per-k reduce partials -> mag -> rowsum -> R[k]; last block finishes the
// global sum (deterministic tree order) and writes the output.
// grid 128 x 128 threads.
// ---------------------------------------------------------------------------
__global__ __launch_bounds__(128) void k3_rate(float* __restrict__ out)
{
    const int k = blockIdx.x;
    const int n = threadIdx.x;

    float gre = 0.f, gim = 0.f;
#pragma unroll 8
    for (int p = 0; p < NMC; p++) {
        gre += d_gp_re[p * (KU * NU) + k * NU + n];
        gim += d_gp_im[p * (KU * NU) + k * NU + n];
    }
    const float mag = sqrtf(gre * gre + gim * gim);

    __shared__ float red[128];
    __shared__ float sig_s;
    __shared__ unsigned int last_s;
    red[n] = mag;
    if (n == k) sig_s = mag;
    __syncthreads();
#pragma unroll
    for (int s = 64; s > 0; s >>= 1) {
        if (n < s) red[n] += red[n + s];
        __syncthreads();
    }
    if (n == 0) {
        const float sig = sig_s;
        d_R[k] = sig / (red[0] - sig + N0F);
        __threadfence();
        last_s = atomicAdd(&d_ctr, 1u);
    }
    __syncthreads();

    if (last_s == KU - 1) {
        // this is the last block: all d_R[] are globally visible
        __threadfence();
        red[n] = d_R[n];
        __syncthreads();
#pragma unroll
        for (int s = 64; s > 0; s >>= 1) {
            if (n < s) red[n] += red[n + s];
            __syncthreads();
        }
        if (n == 0) {
            out[0] = -red[0] * 1e6f;
            d_ctr = 0;   // reset for next graph replay
        }
    }
}

// ---------------------------------------------------------------------------
extern "C" void kernel_launch(void* const* d_in, const int* in_sizes, int n_in,
                              void* d_out, int out_size)
{
    const float* Wv  = (const float*)d_in[0];  // (1025, 256)
    const float* Ar  = (const float*)d_in[1];  // (128, 1024, 128)
    const float* Ai  = (const float*)d_in[2];
    const float* hdr = (const float*)d_in[3];  // (128, 1024)
    const float* hdi = (const float*)d_in[4];

    k12_fused<<<dim3(NMC, NKT), 256>>>(Wv, Ar, Ai, hdr, hdi);
    k3_rate<<<KU, 128>>>((float*)d_out);
}